// round 9
// baseline (speedup 1.0000x reference)
#include <cuda_runtime.h>

#define FULL 0xffffffffu
#define KWARPS 8
#define TPB (KWARPS * 32)

// per-warp scratch (bytes): xks 640 | featS 576 | z1 256 | z2 512 | z3 256 | kS 32
#define WSCR_BYTES 2304

__global__ __launch_bounds__(TPB, 3) void controller_kernel(
    const float* __restrict__ states, const float* __restrict__ goals,
    const float* __restrict__ W1, const float* __restrict__ b1,
    const float* __restrict__ W2, const float* __restrict__ b2,
    const float* __restrict__ Wd1, const float* __restrict__ bd1,
    const float* __restrict__ Wd2, const float* __restrict__ bd2,
    const float* __restrict__ Wd3, const float* __restrict__ bd3,
    const float* __restrict__ Wd4, const float* __restrict__ bd4,
    float* __restrict__ out, int n)
{
    extern __shared__ char smem_raw[];
    float* W2s = (float*)smem_raw;                 // 8192 floats
    float* W1s = W2s + 8192;                       // 320
    float* b1s = W1s + 320;                        // 64
    float* b2s = b1s + 64;                         // 128
    char*  scratch = (char*)(b2s + 128);           // KWARPS * WSCR_BYTES

    const int tid  = threadIdx.x;
    const int lane = tid & 31;
    const int warp = tid >> 5;

    const float4* st4 = (const float4*)states;

    // ---- cooperative staging (weights only; states served from L1) ----
    for (int j = tid; j < 8192; j += TPB) W2s[j] = W2[j];
    for (int j = tid; j < 320;  j += TPB) W1s[j] = W1[j];
    for (int j = tid; j < 64;   j += TPB) b1s[j] = b1[j];
    for (int j = tid; j < 128;  j += TPB) b2s[j] = b2[j];
    __syncthreads();

    const int i = blockIdx.x * KWARPS + warp;
    if (i >= n) return;

    char*  wbase = scratch + warp * WSCR_BYTES;
    float* xks   = (float*)wbase;              // 160 floats
    float* featS = (float*)(wbase + 640);      // 136 (padded)
    float* z1s   = (float*)(wbase + 1216);     // 64
    float* z2s   = (float*)(wbase + 1472);     // 128
    float* z3s   = (float*)(wbase + 1984);     // 64
    float* kS    = (float*)(wbase + 2240);     // 4

    const float4 si = st4[i];
    const float six = si.x, siy = si.y;

    // key for neighbor j: (bits(d) << 32) | j  — distinct, d-then-index order
    auto make_key = [&](int j) -> unsigned long long {
        const float2 p = *(const float2*)(states + 4 * j);
        const float dx = six - p.x;
        const float dy = siy - p.y;
        const float d2 = __fadd_rn(__fadd_rn(__fmul_rn(dx, dx), __fmul_rn(dy, dy)), 1e-4f);
        const float d  = __fsqrt_rn(d2);
        return ((unsigned long long)__float_as_uint(d) << 32) | (unsigned)j;
    };

    // ---------------- Phase 1: top-32 nearest ------------------------------
    // Seed: bitonic-sort batch 0 (32 keys) ascending across lanes.
    unsigned long long R = make_key(lane);
#pragma unroll
    for (int k = 2; k <= 32; k <<= 1) {
#pragma unroll
        for (int jj = k >> 1; jj > 0; jj >>= 1) {
            const unsigned long long other = __shfl_xor_sync(FULL, R, jj);
            const bool dirUp   = ((lane & k) == 0);
            const bool lower   = ((lane & jj) == 0);
            const bool takeMin = (lower == dirUp);
            const unsigned long long mn = (R < other) ? R : other;
            const unsigned long long mx = (R < other) ? other : R;
            R = takeMin ? mn : mx;
        }
    }
    unsigned long long keyMax = __shfl_sync(FULL, R, 31);

    // Remaining batches: ballot early-reject + serial sorted insert.
    // keyMax refreshed once per batch (stale threshold => harmless no-op inserts).
#pragma unroll 2
    for (int base = 32; base < n; base += 32) {
        const unsigned long long key = make_key(base + lane);
        unsigned cm = __ballot_sync(FULL, key < keyMax);
        if (cm) {
            do {
                const int c = __ffs(cm) - 1;
                cm &= cm - 1;
                const unsigned long long k = __shfl_sync(FULL, key, c);
                const int pos = __popc(__ballot_sync(FULL, R < k));
                const unsigned long long up = __shfl_up_sync(FULL, R, 1);
                R = (lane < pos) ? R : (lane == pos ? k : up);
            } while (cm);
            keyMax = __shfl_sync(FULL, R, 31);
        }
    }

    // ---------------- Phase 2: gather neighbor features ---------------------
    const int j = (int)(unsigned)(R & 0xffffffffull);   // lane = neighbor rank
    const float4 sj = st4[j];
    const float x0 = si.x - sj.x;
    const float x1 = si.y - sj.y;
    const float x2 = si.z - sj.z;
    const float x3 = si.w - sj.w;
    const float x4 = (j == i) ? 1.0f : 0.0f;
    const float dist = __fsqrt_rn(__fadd_rn(__fmul_rn(x0, x0), __fmul_rn(x1, x1)));
    const float msk  = (dist < 1.0f) ? 1.0f : 0.0f;

    xks[lane * 5 + 0] = x0;
    xks[lane * 5 + 1] = x1;
    xks[lane * 5 + 2] = x2;
    xks[lane * 5 + 3] = x3;
    xks[lane * 5 + 4] = x4;
    __syncwarp();

    // raw reshape [32,5] -> [5,32]: lane = position p
    const float h0 = xks[  0 + lane];
    const float h1 = xks[ 32 + lane];
    const float h2 = xks[ 64 + lane];
    const float h3 = xks[ 96 + lane];
    const float h4 = xks[128 + lane];

    // ---------------- Phase 3a: conv1 5 -> 64 (relu) ------------------------
    float o1[64];
#pragma unroll
    for (int o = 0; o < 64; ++o) {
        const float* w = W1s + o * 5;
        float a = __fmul_rn(w[0], h0);
        a = fmaf(w[1], h1, a);
        a = fmaf(w[2], h2, a);
        a = fmaf(w[3], h3, a);
        a = fmaf(w[4], h4, a);
        a = __fadd_rn(a, b1s[o]);
        o1[o] = fmaxf(a, 0.0f);
    }

    // ---------------- Phase 3b: conv2 64 -> 128 + masked argmax -------------
    // Two q-channels in flight: independent accumulator chains; per-q fmaf
    // order (c = 0..63) identical to the monolithic version -> bitwise exact.
    for (int q = 0; q < 128; q += 2) {
        const float4* w0 = (const float4*)(W2s + (q    ) * 64);
        const float4* w1 = (const float4*)(W2s + (q + 1) * 64);
        float a0 = 0.0f, a1 = 0.0f;
#pragma unroll
        for (int t = 0; t < 16; ++t) {
            const float4 wa = w0[t];
            const float4 wb = w1[t];
            a0 = fmaf(wa.x, o1[4 * t + 0], a0);
            a0 = fmaf(wa.y, o1[4 * t + 1], a0);
            a0 = fmaf(wa.z, o1[4 * t + 2], a0);
            a0 = fmaf(wa.w, o1[4 * t + 3], a0);
            a1 = fmaf(wb.x, o1[4 * t + 0], a1);
            a1 = fmaf(wb.y, o1[4 * t + 1], a1);
            a1 = fmaf(wb.z, o1[4 * t + 2], a1);
            a1 = fmaf(wb.w, o1[4 * t + 3], a1);
        }
#pragma unroll
        for (int s = 0; s < 2; ++s) {
            float a = s ? a1 : a0;
            const int qq = q + s;
            a = __fadd_rn(a, b2s[qq]);
            a = fmaxf(a, 0.0f);
            const float v = __fmul_rn(a, msk);        // v >= 0
            const unsigned vb   = __float_as_uint(v); // monotonic for v >= 0
            const unsigned vmax = __reduce_max_sync(FULL, vb);
            const int bp = __ffs(__ballot_sync(FULL, vb == vmax)) - 1;
            if (lane == 0) featS[qq] = (float)bp;
        }
    }

    // ---------------- Phase 4: MLP 132 -> 64 -> 128 -> 64 -> 4 --------------
    if (lane == 0) {
        const float2 g = ((const float2*)goals)[i];
        featS[128] = si.x - g.x;
        featS[129] = si.y - g.y;
        featS[130] = si.z;
        featS[131] = si.w;
    }
    __syncwarp();

#pragma unroll
    for (int r = 0; r < 2; ++r) {
        const int nn = lane + 32 * r;
        const float4* w  = (const float4*)(Wd1 + nn * 132);
        const float4* f4 = (const float4*)featS;
        float a = 0.0f;
#pragma unroll
        for (int t = 0; t < 33; ++t) {
            const float4 wv = w[t];
            const float4 fv = f4[t];
            a = fmaf(wv.x, fv.x, a); a = fmaf(wv.y, fv.y, a);
            a = fmaf(wv.z, fv.z, a); a = fmaf(wv.w, fv.w, a);
        }
        a = __fadd_rn(a, bd1[nn]);
        z1s[nn] = fmaxf(a, 0.0f);
    }
    __syncwarp();

#pragma unroll
    for (int r = 0; r < 4; ++r) {
        const int nn = lane + 32 * r;
        const float4* w  = (const float4*)(Wd2 + nn * 64);
        const float4* f4 = (const float4*)z1s;
        float a = 0.0f;
#pragma unroll
        for (int t = 0; t < 16; ++t) {
            const float4 wv = w[t];
            const float4 fv = f4[t];
            a = fmaf(wv.x, fv.x, a); a = fmaf(wv.y, fv.y, a);
            a = fmaf(wv.z, fv.z, a); a = fmaf(wv.w, fv.w, a);
        }
        a = __fadd_rn(a, bd2[nn]);
        z2s[nn] = fmaxf(a, 0.0f);
    }
    __syncwarp();

#pragma unroll
    for (int r = 0; r < 2; ++r) {
        const int nn = lane + 32 * r;
        const float4* w  = (const float4*)(Wd3 + nn * 128);
        const float4* f4 = (const float4*)z2s;
        float a = 0.0f;
#pragma unroll
        for (int t = 0; t < 32; ++t) {
            const float4 wv = w[t];
            const float4 fv = f4[t];
            a = fmaf(wv.x, fv.x, a); a = fmaf(wv.y, fv.y, a);
            a = fmaf(wv.z, fv.z, a); a = fmaf(wv.w, fv.w, a);
        }
        a = __fadd_rn(a, bd3[nn]);
        z3s[nn] = fmaxf(a, 0.0f);
    }
    __syncwarp();

    if (lane < 4) {
        const float4* w  = (const float4*)(Wd4 + lane * 64);
        const float4* f4 = (const float4*)z3s;
        float a = 0.0f;
#pragma unroll
        for (int t = 0; t < 16; ++t) {
            const float4 wv = w[t];
            const float4 fv = f4[t];
            a = fmaf(wv.x, fv.x, a); a = fmaf(wv.y, fv.y, a);
            a = fmaf(wv.z, fv.z, a); a = fmaf(wv.w, fv.w, a);
        }
        a = __fadd_rn(a, bd4[lane]);
        kS[lane] = 2.0f / (1.0f + expf(-a)) + 0.2f;
    }
    __syncwarp();

    if (lane == 0) {
        const float k0 = kS[0], k1 = kS[1], k2 = kS[2], k3 = kS[3];
        const float relx = featS[128], rely = featS[129];
        const float vx = si.z, vy = si.w;
        const float ax = -__fadd_rn(__fmul_rn(k0, relx), __fmul_rn(k1, vx));
        const float ay = -__fadd_rn(__fmul_rn(k2, rely), __fmul_rn(k3, vy));
        ((float2*)out)[i] = make_float2(ax, ay);
    }
}

extern "C" void kernel_launch(void* const* d_in, const int* in_sizes, int n_in,
                              void* d_out, int out_size)
{
    const float* states = (const float*)d_in[0];
    const float* goals  = (const float*)d_in[1];
    const float* W1  = (const float*)d_in[2];
    const float* b1  = (const float*)d_in[3];
    const float* W2  = (const float*)d_in[4];
    const float* b2  = (const float*)d_in[5];
    const float* Wd1 = (const float*)d_in[6];
    const float* bd1 = (const float*)d_in[7];
    const float* Wd2 = (const float*)d_in[8];
    const float* bd2 = (const float*)d_in[9];
    const float* Wd3 = (const float*)d_in[10];
    const float* bd3 = (const float*)d_in[11];
    const float* Wd4 = (const float*)d_in[12];
    const float* bd4 = (const float*)d_in[13];

    const int n = in_sizes[0] / 4;
    const int blocks = (n + KWARPS - 1) / KWARPS;
    const size_t smem = (8192 + 320 + 64 + 128) * sizeof(float)
                      + (size_t)KWARPS * WSCR_BYTES;

    cudaFuncSetAttribute(controller_kernel,
                         cudaFuncAttributeMaxDynamicSharedMemorySize, (int)smem);

    controller_kernel<<<blocks, TPB, smem>>>(
        states, goals, W1, b1, W2, b2,
        Wd1, bd1, Wd2, bd2, Wd3, bd3, Wd4, bd4,
        (float*)d_out, n);
}

// round 10
// speedup vs baseline: 1.1600x; 1.1600x over previous
#include <cuda_runtime.h>

#define FULL 0xffffffffu
#define KWARPS 8
#define TPB (KWARPS * 32)

// per-warp scratch (bytes): xks 640 | featS 576 | z1 256 | z2 512 | z3 256 | kS 32
#define WSCR_BYTES 2304

__global__ __launch_bounds__(TPB, 2) void controller_kernel(
    const float* __restrict__ states, const float* __restrict__ goals,
    const float* __restrict__ W1, const float* __restrict__ b1,
    const float* __restrict__ W2, const float* __restrict__ b2,
    const float* __restrict__ Wd1, const float* __restrict__ bd1,
    const float* __restrict__ Wd2, const float* __restrict__ bd2,
    const float* __restrict__ Wd3, const float* __restrict__ bd3,
    const float* __restrict__ Wd4, const float* __restrict__ bd4,
    float* __restrict__ out, int n)
{
    extern __shared__ char smem_raw[];
    float* W2s = (float*)smem_raw;                 // 8192 floats
    float* W1s = W2s + 8192;                       // 320
    float* b1s = W1s + 320;                        // 64
    float* b2s = b1s + 64;                         // 128
    char*  scratch = (char*)(b2s + 128);           // KWARPS * WSCR_BYTES

    const int tid  = threadIdx.x;
    const int lane = tid & 31;
    const int warp = tid >> 5;

    const float4* st4 = (const float4*)states;

    // ---- cooperative staging (weights only; states served from L1) ----
    for (int j = tid; j < 8192; j += TPB) W2s[j] = W2[j];
    for (int j = tid; j < 320;  j += TPB) W1s[j] = W1[j];
    for (int j = tid; j < 64;   j += TPB) b1s[j] = b1[j];
    for (int j = tid; j < 128;  j += TPB) b2s[j] = b2[j];
    __syncthreads();

    const int i = blockIdx.x * KWARPS + warp;
    if (i >= n) return;

    char*  wbase = scratch + warp * WSCR_BYTES;
    float* xks   = (float*)wbase;              // 160 floats
    float* featS = (float*)(wbase + 640);      // 136 (padded)
    float* z1s   = (float*)(wbase + 1216);     // 64
    float* z2s   = (float*)(wbase + 1472);     // 128
    float* z3s   = (float*)(wbase + 1984);     // 64
    float* kS    = (float*)(wbase + 2240);     // 4

    const float4 si = st4[i];
    const float six = si.x, siy = si.y;

    // key for neighbor j: (bits(d) << 32) | j  — distinct, d-then-index order
    auto make_key = [&](int j) -> unsigned long long {
        const float2 p = *(const float2*)(states + 4 * j);
        const float dx = six - p.x;
        const float dy = siy - p.y;
        const float d2 = __fadd_rn(__fadd_rn(__fmul_rn(dx, dx), __fmul_rn(dy, dy)), 1e-4f);
        const float d  = __fsqrt_rn(d2);
        return ((unsigned long long)__float_as_uint(d) << 32) | (unsigned)j;
    };

    // ---------------- Phase 1: top-32 nearest ------------------------------
    // Seed: bitonic-sort batch 0 (32 keys) ascending across lanes.
    unsigned long long R = make_key(lane);
#pragma unroll
    for (int k = 2; k <= 32; k <<= 1) {
#pragma unroll
        for (int jj = k >> 1; jj > 0; jj >>= 1) {
            const unsigned long long other = __shfl_xor_sync(FULL, R, jj);
            const bool dirUp   = ((lane & k) == 0);
            const bool lower   = ((lane & jj) == 0);
            const bool takeMin = (lower == dirUp);
            const unsigned long long mn = (R < other) ? R : other;
            const unsigned long long mx = (R < other) ? other : R;
            R = takeMin ? mn : mx;
        }
    }
    unsigned long long keyMax = __shfl_sync(FULL, R, 31);

    // Remaining batches: ballot early-reject + serial sorted insert.
    // keyMax refreshed once per batch (stale threshold => harmless no-op inserts).
#pragma unroll 2
    for (int base = 32; base < n; base += 32) {
        const unsigned long long key = make_key(base + lane);
        unsigned cm = __ballot_sync(FULL, key < keyMax);
        if (cm) {
            do {
                const int c = __ffs(cm) - 1;
                cm &= cm - 1;
                const unsigned long long k = __shfl_sync(FULL, key, c);
                const int pos = __popc(__ballot_sync(FULL, R < k));
                const unsigned long long up = __shfl_up_sync(FULL, R, 1);
                R = (lane < pos) ? R : (lane == pos ? k : up);
            } while (cm);
            keyMax = __shfl_sync(FULL, R, 31);
        }
    }

    // ---------------- Phase 2: gather neighbor features ---------------------
    const int j = (int)(unsigned)(R & 0xffffffffull);   // lane = neighbor rank
    const float4 sj = st4[j];
    const float x0 = si.x - sj.x;
    const float x1 = si.y - sj.y;
    const float x2 = si.z - sj.z;
    const float x3 = si.w - sj.w;
    const float x4 = (j == i) ? 1.0f : 0.0f;
    const float dist = __fsqrt_rn(__fadd_rn(__fmul_rn(x0, x0), __fmul_rn(x1, x1)));
    const float msk  = (dist < 1.0f) ? 1.0f : 0.0f;

    xks[lane * 5 + 0] = x0;
    xks[lane * 5 + 1] = x1;
    xks[lane * 5 + 2] = x2;
    xks[lane * 5 + 3] = x3;
    xks[lane * 5 + 4] = x4;
    __syncwarp();

    // raw reshape [32,5] -> [5,32]: lane = position p
    const float h0 = xks[  0 + lane];
    const float h1 = xks[ 32 + lane];
    const float h2 = xks[ 64 + lane];
    const float h3 = xks[ 96 + lane];
    const float h4 = xks[128 + lane];

    // ---------------- Phase 3a: conv1 5 -> 64 (relu) ------------------------
    float o1[64];
#pragma unroll
    for (int o = 0; o < 64; ++o) {
        const float* w = W1s + o * 5;
        float a = __fmul_rn(w[0], h0);
        a = fmaf(w[1], h1, a);
        a = fmaf(w[2], h2, a);
        a = fmaf(w[3], h3, a);
        a = fmaf(w[4], h4, a);
        a = __fadd_rn(a, b1s[o]);
        o1[o] = fmaxf(a, 0.0f);
    }

    // ---------------- Phase 3b: conv2 64 -> 128 + masked argmax -------------
    // FOUR q-channels in flight: independent accumulator chains; per-q fmaf
    // order (c = 0..63 ascending, bias last) identical to the monolithic
    // version -> bitwise exact. Four argmax epilogues overlap their latency.
    for (int q = 0; q < 128; q += 4) {
        const float4* w0 = (const float4*)(W2s + (q    ) * 64);
        const float4* w1 = (const float4*)(W2s + (q + 1) * 64);
        const float4* w2 = (const float4*)(W2s + (q + 2) * 64);
        const float4* w3 = (const float4*)(W2s + (q + 3) * 64);
        float a0 = 0.0f, a1 = 0.0f, a2 = 0.0f, a3 = 0.0f;
#pragma unroll
        for (int t = 0; t < 16; ++t) {
            const float4 wa = w0[t];
            const float4 wb = w1[t];
            const float4 wc = w2[t];
            const float4 wd = w3[t];
            const float v0 = o1[4 * t + 0];
            const float v1 = o1[4 * t + 1];
            const float v2 = o1[4 * t + 2];
            const float v3 = o1[4 * t + 3];
            a0 = fmaf(wa.x, v0, a0); a0 = fmaf(wa.y, v1, a0);
            a0 = fmaf(wa.z, v2, a0); a0 = fmaf(wa.w, v3, a0);
            a1 = fmaf(wb.x, v0, a1); a1 = fmaf(wb.y, v1, a1);
            a1 = fmaf(wb.z, v2, a1); a1 = fmaf(wb.w, v3, a1);
            a2 = fmaf(wc.x, v0, a2); a2 = fmaf(wc.y, v1, a2);
            a2 = fmaf(wc.z, v2, a2); a2 = fmaf(wc.w, v3, a2);
            a3 = fmaf(wd.x, v0, a3); a3 = fmaf(wd.y, v1, a3);
            a3 = fmaf(wd.z, v2, a3); a3 = fmaf(wd.w, v3, a3);
        }
        float acc[4] = {a0, a1, a2, a3};
#pragma unroll
        for (int s = 0; s < 4; ++s) {
            float a = acc[s];
            const int qq = q + s;
            a = __fadd_rn(a, b2s[qq]);
            a = fmaxf(a, 0.0f);
            const float v = __fmul_rn(a, msk);        // v >= 0
            const unsigned vb   = __float_as_uint(v); // monotonic for v >= 0
            const unsigned vmax = __reduce_max_sync(FULL, vb);
            const int bp = __ffs(__ballot_sync(FULL, vb == vmax)) - 1;
            if (lane == 0) featS[qq] = (float)bp;
        }
    }

    // ---------------- Phase 4: MLP 132 -> 64 -> 128 -> 64 -> 4 --------------
    if (lane == 0) {
        const float2 g = ((const float2*)goals)[i];
        featS[128] = si.x - g.x;
        featS[129] = si.y - g.y;
        featS[130] = si.z;
        featS[131] = si.w;
    }
    __syncwarp();

#pragma unroll
    for (int r = 0; r < 2; ++r) {
        const int nn = lane + 32 * r;
        const float4* w  = (const float4*)(Wd1 + nn * 132);
        const float4* f4 = (const float4*)featS;
        float a = 0.0f;
#pragma unroll
        for (int t = 0; t < 33; ++t) {
            const float4 wv = w[t];
            const float4 fv = f4[t];
            a = fmaf(wv.x, fv.x, a); a = fmaf(wv.y, fv.y, a);
            a = fmaf(wv.z, fv.z, a); a = fmaf(wv.w, fv.w, a);
        }
        a = __fadd_rn(a, bd1[nn]);
        z1s[nn] = fmaxf(a, 0.0f);
    }
    __syncwarp();

#pragma unroll
    for (int r = 0; r < 4; ++r) {
        const int nn = lane + 32 * r;
        const float4* w  = (const float4*)(Wd2 + nn * 64);
        const float4* f4 = (const float4*)z1s;
        float a = 0.0f;
#pragma unroll
        for (int t = 0; t < 16; ++t) {
            const float4 wv = w[t];
            const float4 fv = f4[t];
            a = fmaf(wv.x, fv.x, a); a = fmaf(wv.y, fv.y, a);
            a = fmaf(wv.z, fv.z, a); a = fmaf(wv.w, fv.w, a);
        }
        a = __fadd_rn(a, bd2[nn]);
        z2s[nn] = fmaxf(a, 0.0f);
    }
    __syncwarp();

#pragma unroll
    for (int r = 0; r < 2; ++r) {
        const int nn = lane + 32 * r;
        const float4* w  = (const float4*)(Wd3 + nn * 128);
        const float4* f4 = (const float4*)z2s;
        float a = 0.0f;
#pragma unroll
        for (int t = 0; t < 32; ++t) {
            const float4 wv = w[t];
            const float4 fv = f4[t];
            a = fmaf(wv.x, fv.x, a); a = fmaf(wv.y, fv.y, a);
            a = fmaf(wv.z, fv.z, a); a = fmaf(wv.w, fv.w, a);
        }
        a = __fadd_rn(a, bd3[nn]);
        z3s[nn] = fmaxf(a, 0.0f);
    }
    __syncwarp();

    if (lane < 4) {
        const float4* w  = (const float4*)(Wd4 + lane * 64);
        const float4* f4 = (const float4*)z3s;
        float a = 0.0f;
#pragma unroll
        for (int t = 0; t < 16; ++t) {
            const float4 wv = w[t];
            const float4 fv = f4[t];
            a = fmaf(wv.x, fv.x, a); a = fmaf(wv.y, fv.y, a);
            a = fmaf(wv.z, fv.z, a); a = fmaf(wv.w, fv.w, a);
        }
        a = __fadd_rn(a, bd4[lane]);
        kS[lane] = 2.0f / (1.0f + expf(-a)) + 0.2f;
    }
    __syncwarp();

    if (lane == 0) {
        const float k0 = kS[0], k1 = kS[1], k2 = kS[2], k3 = kS[3];
        const float relx = featS[128], rely = featS[129];
        const float vx = si.z, vy = si.w;
        const float ax = -__fadd_rn(__fmul_rn(k0, relx), __fmul_rn(k1, vx));
        const float ay = -__fadd_rn(__fmul_rn(k2, rely), __fmul_rn(k3, vy));
        ((float2*)out)[i] = make_float2(ax, ay);
    }
}

extern "C" void kernel_launch(void* const* d_in, const int* in_sizes, int n_in,
                              void* d_out, int out_size)
{
    const float* states = (const float*)d_in[0];
    const float* goals  = (const float*)d_in[1];
    const float* W1  = (const float*)d_in[2];
    const float* b1  = (const float*)d_in[3];
    const float* W2  = (const float*)d_in[4];
    const float* b2  = (const float*)d_in[5];
    const float* Wd1 = (const float*)d_in[6];
    const float* bd1 = (const float*)d_in[7];
    const float* Wd2 = (const float*)d_in[8];
    const float* bd2 = (const float*)d_in[9];
    const float* Wd3 = (const float*)d_in[10];
    const float* bd3 = (const float*)d_in[11];
    const float* Wd4 = (const float*)d_in[12];
    const float* bd4 = (const float*)d_in[13];

    const int n = in_sizes[0] / 4;
    const int blocks = (n + KWARPS - 1) / KWARPS;
    const size_t smem = (8192 + 320 + 64 + 128) * sizeof(float)
                      + (size_t)KWARPS * WSCR_BYTES;

    cudaFuncSetAttribute(controller_kernel,
                         cudaFuncAttributeMaxDynamicSharedMemorySize, (int)smem);

    controller_kernel<<<blocks, TPB, smem>>>(
        states, goals, W1, b1, W2, b2,
        Wd1, bd1, Wd2, bd2, Wd3, bd3, Wd4, bd4,
        (float*)d_out, n);
}

// round 11
// speedup vs baseline: 1.2079x; 1.0413x over previous
#include <cuda_runtime.h>

#define FULL 0xffffffffu
#define KWARPS 8
#define TPB (KWARPS * 32)

// shared layout (floats):
//  O1s   [64][256]      16384   conv1 outputs, row=c, col=agent*32+pos
//  W2Ts  [64][132]pad    8448   W2 transposed, row=c, col=q (128 used, pad 132)
//  W1s   320 | b1s 64 | b2s 128
//  msks  [256]
//  featS [8][132]        1056
//  wscr  8 x 272         2176   (xks 160 aliased later by z1/z2/z3/kS)
#define WSCR_FLOATS 272

__global__ __launch_bounds__(TPB, 2) void controller_kernel(
    const float* __restrict__ states, const float* __restrict__ goals,
    const float* __restrict__ W1, const float* __restrict__ b1,
    const float* __restrict__ W2, const float* __restrict__ b2,
    const float* __restrict__ Wd1, const float* __restrict__ bd1,
    const float* __restrict__ Wd2, const float* __restrict__ bd2,
    const float* __restrict__ Wd3, const float* __restrict__ bd3,
    const float* __restrict__ Wd4, const float* __restrict__ bd4,
    float* __restrict__ out, int n)
{
    extern __shared__ float smem[];
    float* O1s   = smem;                   // 16384
    float* W2Ts  = O1s + 16384;            // 8448  (row stride 132)
    float* W1s   = W2Ts + 8448;            // 320
    float* b1s   = W1s + 320;              // 64
    float* b2s   = b1s + 64;               // 128
    float* msks  = b2s + 128;              // 256
    float* featS = msks + 256;             // 1056 (8 x 132)
    float* wscr0 = featS + 1056;           // 8 x 272

    const int tid  = threadIdx.x;
    const int lane = tid & 31;
    const int warp = tid >> 5;

    const float4* st4 = (const float4*)states;

    // ---- staging: W2 transposed (coalesced read, mildly-conflicted STS) ----
    for (int idx = tid; idx < 8192; idx += TPB) {
        const int q = idx >> 6, c = idx & 63;
        W2Ts[c * 132 + q] = W2[idx];
    }
    for (int j = tid; j < 320; j += TPB) W1s[j] = W1[j];
    for (int j = tid; j < 64;  j += TPB) b1s[j] = b1[j];
    for (int j = tid; j < 128; j += TPB) b2s[j] = b2[j];
    __syncthreads();

    const int i = blockIdx.x * KWARPS + warp;
    const bool active = (i < n);

    float* wscr = wscr0 + warp * WSCR_FLOATS;
    float* xks  = wscr;          // 160 (dead after conv1)
    float* z1s  = wscr;          // 64  (aliases xks)
    float* z2s  = wscr + 64;     // 128
    float* z3s  = wscr + 192;    // 64
    float* kS   = wscr + 256;    // 4

    float4 si = make_float4(0.f, 0.f, 0.f, 0.f);

    if (active) {
        si = st4[i];
        const float six = si.x, siy = si.y;

        auto make_key = [&](int j) -> unsigned long long {
            const float2 p = *(const float2*)(states + 4 * j);
            const float dx = six - p.x;
            const float dy = siy - p.y;
            const float d2 = __fadd_rn(__fadd_rn(__fmul_rn(dx, dx), __fmul_rn(dy, dy)), 1e-4f);
            const float d  = __fsqrt_rn(d2);
            return ((unsigned long long)__float_as_uint(d) << 32) | (unsigned)j;
        };

        // ---------------- Phase 1: top-32 nearest --------------------------
        unsigned long long R = make_key(lane);
#pragma unroll
        for (int k = 2; k <= 32; k <<= 1) {
#pragma unroll
            for (int jj = k >> 1; jj > 0; jj >>= 1) {
                const unsigned long long other = __shfl_xor_sync(FULL, R, jj);
                const bool takeMin = (((lane & jj) == 0) == ((lane & k) == 0));
                const unsigned long long mn = (R < other) ? R : other;
                const unsigned long long mx = (R < other) ? other : R;
                R = takeMin ? mn : mx;
            }
        }
        unsigned long long keyMax = __shfl_sync(FULL, R, 31);

#pragma unroll 2
        for (int base = 32; base < n; base += 32) {
            const unsigned long long key = make_key(base + lane);
            unsigned cm = __ballot_sync(FULL, key < keyMax);
            if (cm) {
                do {
                    const int c = __ffs(cm) - 1;
                    cm &= cm - 1;
                    const unsigned long long k = __shfl_sync(FULL, key, c);
                    const int pos = __popc(__ballot_sync(FULL, R < k));
                    const unsigned long long up = __shfl_up_sync(FULL, R, 1);
                    R = (lane < pos) ? R : (lane == pos ? k : up);
                } while (cm);
                keyMax = __shfl_sync(FULL, R, 31);
            }
        }

        // ---------------- Phase 2: neighbor features -----------------------
        const int j = (int)(unsigned)(R & 0xffffffffull);
        const float4 sj = st4[j];
        const float x0 = si.x - sj.x;
        const float x1 = si.y - sj.y;
        const float x2 = si.z - sj.z;
        const float x3 = si.w - sj.w;
        const float x4 = (j == i) ? 1.0f : 0.0f;
        const float dist = __fsqrt_rn(__fadd_rn(__fmul_rn(x0, x0), __fmul_rn(x1, x1)));
        msks[32 * warp + lane] = (dist < 1.0f) ? 1.0f : 0.0f;

        xks[lane * 5 + 0] = x0;
        xks[lane * 5 + 1] = x1;
        xks[lane * 5 + 2] = x2;
        xks[lane * 5 + 3] = x3;
        xks[lane * 5 + 4] = x4;
        __syncwarp();

        // raw reshape [32,5] -> [5,32]: lane = position p
        const float h0 = xks[  0 + lane];
        const float h1 = xks[ 32 + lane];
        const float h2 = xks[ 64 + lane];
        const float h3 = xks[ 96 + lane];
        const float h4 = xks[128 + lane];

        // ---------------- Phase 3a: conv1 5 -> 64, straight to shared ------
        const int col = 32 * warp + lane;
#pragma unroll 8
        for (int c = 0; c < 64; ++c) {
            const float* w = W1s + c * 5;
            float a = __fmul_rn(w[0], h0);
            a = fmaf(w[1], h1, a);
            a = fmaf(w[2], h2, a);
            a = fmaf(w[3], h3, a);
            a = fmaf(w[4], h4, a);
            a = __fadd_rn(a, b1s[c]);
            O1s[c * 256 + col] = fmaxf(a, 0.0f);
        }

        // rel/vel tail of the feature vector
        if (lane == 0) {
            const float2 g = ((const float2*)goals)[i];
            float* fA = featS + warp * 132;
            fA[128] = si.x - g.x;
            fA[129] = si.y - g.y;
            fA[130] = si.z;
            fA[131] = si.w;
        }
    }
    __syncthreads();

    // ---------------- Phase 3b: block GEMM (128q x 256col, k=64) -----------
    // warp = q-group (8 q per warp per pass), lane = col-group (8 cols).
    // Per output: single fp32 accumulator, c ascending, bias last — bitwise
    // identical to the monolithic per-warp version.
    {
        float mk[8];
        {
            const float4 m0 = *(const float4*)(msks + lane * 8);
            const float4 m1 = *(const float4*)(msks + lane * 8 + 4);
            mk[0] = m0.x; mk[1] = m0.y; mk[2] = m0.z; mk[3] = m0.w;
            mk[4] = m1.x; mk[5] = m1.y; mk[6] = m1.z; mk[7] = m1.w;
        }
        const int agent = lane >> 2;            // agent within block
        const int psub  = (lane & 3) * 8;       // first position of this thread

        for (int pass = 0; pass < 2; ++pass) {
            const int qbase = pass * 64 + warp * 8;
            float acc[8][8];
#pragma unroll
            for (int a = 0; a < 8; ++a)
#pragma unroll
                for (int b = 0; b < 8; ++b) acc[a][b] = 0.0f;

            const float* wp = W2Ts + qbase;
            const float* op = O1s + lane * 8;
#pragma unroll 2
            for (int c = 0; c < 64; ++c) {
                const float4 wv0 = *(const float4*)(wp + c * 132);
                const float4 wv1 = *(const float4*)(wp + c * 132 + 4);
                const float4 ov0 = *(const float4*)(op + c * 256);
                const float4 ov1 = *(const float4*)(op + c * 256 + 4);
                const float wr[8] = {wv0.x, wv0.y, wv0.z, wv0.w,
                                     wv1.x, wv1.y, wv1.z, wv1.w};
                const float orr[8] = {ov0.x, ov0.y, ov0.z, ov0.w,
                                      ov1.x, ov1.y, ov1.z, ov1.w};
#pragma unroll
                for (int a = 0; a < 8; ++a)
#pragma unroll
                    for (int b = 0; b < 8; ++b)
                        acc[a][b] = fmaf(wr[a], orr[b], acc[a][b]);
            }

            // epilogue: bias + relu + mask, argmax over 32 positions
#pragma unroll
            for (int a = 0; a < 8; ++a) {
                const int q = qbase + a;
                const float bq = b2s[q];
                unsigned best = 0u;
                int bp = psub;
#pragma unroll
                for (int b = 0; b < 8; ++b) {
                    const float v = __fmul_rn(
                        fmaxf(__fadd_rn(acc[a][b], bq), 0.0f), mk[b]);
                    const unsigned vb = __float_as_uint(v);
                    if (vb > best) { best = vb; bp = psub + b; }
                }
                unsigned long long key =
                    ((unsigned long long)best << 5) | (unsigned)(31 - bp);
                unsigned long long ok = __shfl_xor_sync(FULL, key, 1);
                key = (ok > key) ? ok : key;
                ok = __shfl_xor_sync(FULL, key, 2);
                key = (ok > key) ? ok : key;
                if ((lane & 3) == 0)
                    featS[agent * 132 + q] = (float)(31 - (int)(key & 31ull));
            }
        }
    }
    __syncthreads();

    // ---------------- Phase 4: MLP 132 -> 64 -> 128 -> 64 -> 4 --------------
    if (!active) return;
    {
        const float* fA = featS + warp * 132;

#pragma unroll
        for (int r = 0; r < 2; ++r) {
            const int nn = lane + 32 * r;
            const float4* w  = (const float4*)(Wd1 + nn * 132);
            const float4* f4 = (const float4*)fA;
            float a = 0.0f;
#pragma unroll
            for (int t = 0; t < 33; ++t) {
                const float4 wv = w[t];
                const float4 fv = f4[t];
                a = fmaf(wv.x, fv.x, a); a = fmaf(wv.y, fv.y, a);
                a = fmaf(wv.z, fv.z, a); a = fmaf(wv.w, fv.w, a);
            }
            a = __fadd_rn(a, bd1[nn]);
            z1s[nn] = fmaxf(a, 0.0f);
        }
        __syncwarp();

#pragma unroll
        for (int r = 0; r < 4; ++r) {
            const int nn = lane + 32 * r;
            const float4* w  = (const float4*)(Wd2 + nn * 64);
            const float4* f4 = (const float4*)z1s;
            float a = 0.0f;
#pragma unroll
            for (int t = 0; t < 16; ++t) {
                const float4 wv = w[t];
                const float4 fv = f4[t];
                a = fmaf(wv.x, fv.x, a); a = fmaf(wv.y, fv.y, a);
                a = fmaf(wv.z, fv.z, a); a = fmaf(wv.w, fv.w, a);
            }
            a = __fadd_rn(a, bd2[nn]);
            z2s[nn] = fmaxf(a, 0.0f);
        }
        __syncwarp();

#pragma unroll
        for (int r = 0; r < 2; ++r) {
            const int nn = lane + 32 * r;
            const float4* w  = (const float4*)(Wd3 + nn * 128);
            const float4* f4 = (const float4*)z2s;
            float a = 0.0f;
#pragma unroll
            for (int t = 0; t < 32; ++t) {
                const float4 wv = w[t];
                const float4 fv = f4[t];
                a = fmaf(wv.x, fv.x, a); a = fmaf(wv.y, fv.y, a);
                a = fmaf(wv.z, fv.z, a); a = fmaf(wv.w, fv.w, a);
            }
            a = __fadd_rn(a, bd3[nn]);
            z3s[nn] = fmaxf(a, 0.0f);
        }
        __syncwarp();

        if (lane < 4) {
            const float4* w  = (const float4*)(Wd4 + lane * 64);
            const float4* f4 = (const float4*)z3s;
            float a = 0.0f;
#pragma unroll
            for (int t = 0; t < 16; ++t) {
                const float4 wv = w[t];
                const float4 fv = f4[t];
                a = fmaf(wv.x, fv.x, a); a = fmaf(wv.y, fv.y, a);
                a = fmaf(wv.z, fv.z, a); a = fmaf(wv.w, fv.w, a);
            }
            a = __fadd_rn(a, bd4[lane]);
            kS[lane] = 2.0f / (1.0f + expf(-a)) + 0.2f;
        }
        __syncwarp();

        if (lane == 0) {
            const float k0 = kS[0], k1 = kS[1], k2 = kS[2], k3 = kS[3];
            const float relx = fA[128], rely = fA[129];
            const float vx = si.z, vy = si.w;
            const float ax = -__fadd_rn(__fmul_rn(k0, relx), __fmul_rn(k1, vx));
            const float ay = -__fadd_rn(__fmul_rn(k2, rely), __fmul_rn(k3, vy));
            ((float2*)out)[i] = make_float2(ax, ay);
        }
    }
}

extern "C" void kernel_launch(void* const* d_in, const int* in_sizes, int n_in,
                              void* d_out, int out_size)
{
    const float* states = (const float*)d_in[0];
    const float* goals  = (const float*)d_in[1];
    const float* W1  = (const float*)d_in[2];
    const float* b1  = (const float*)d_in[3];
    const float* W2  = (const float*)d_in[4];
    const float* b2  = (const float*)d_in[5];
    const float* Wd1 = (const float*)d_in[6];
    const float* bd1 = (const float*)d_in[7];
    const float* Wd2 = (const float*)d_in[8];
    const float* bd2 = (const float*)d_in[9];
    const float* Wd3 = (const float*)d_in[10];
    const float* bd3 = (const float*)d_in[11];
    const float* Wd4 = (const float*)d_in[12];
    const float* bd4 = (const float*)d_in[13];

    const int n = in_sizes[0] / 4;
    const int blocks = (n + KWARPS - 1) / KWARPS;
    const size_t smem_floats = 16384 + 8448 + 320 + 64 + 128 + 256 + 1056
                             + (size_t)KWARPS * WSCR_FLOATS;
    const size_t smem = smem_floats * sizeof(float);

    cudaFuncSetAttribute(controller_kernel,
                         cudaFuncAttributeMaxDynamicSharedMemorySize, (int)smem);

    controller_kernel<<<blocks, TPB, smem>>>(
        states, goals, W1, b1, W2, b2,
        Wd1, bd1, Wd2, bd2, Wd3, bd3, Wd4, bd4,
        (float*)d_out, n);
}

// round 12
// speedup vs baseline: 1.5054x; 1.2463x over previous
#include <cuda_runtime.h>

#define FULL 0xffffffffu

// ---------------- scratch for neighbor indices (no allocation) --------------
#define MAXN 8192
__device__ unsigned g_nbr[MAXN * 32];

// ============================================================================
// Kernel A: top-32 nearest neighbors per agent (one warp per agent).
// High occupancy: 512 threads, ~40 regs, 32KB smem -> 8+ warps/SMSP overlap
// the shfl/ballot latency chains.
// ============================================================================
#define A_WARPS 16
#define A_TPB (A_WARPS * 32)

__global__ __launch_bounds__(A_TPB, 2) void topk_kernel(
    const float* __restrict__ states, int n)
{
    extern __shared__ float2 sxy[];
    const int tid  = threadIdx.x;
    const int lane = tid & 31;
    const int warp = tid >> 5;

    for (int j = tid; j < n; j += A_TPB) {
        const float4 s = ((const float4*)states)[j];
        sxy[j] = make_float2(s.x, s.y);
    }
    __syncthreads();

    const int i = blockIdx.x * A_WARPS + warp;
    if (i >= n) return;

    const float2 pi = sxy[i];
    const float six = pi.x, siy = pi.y;

    auto make_key = [&](int j) -> unsigned long long {
        const float2 p = sxy[j];
        const float dx = six - p.x;
        const float dy = siy - p.y;
        const float d2 = __fadd_rn(__fadd_rn(__fmul_rn(dx, dx), __fmul_rn(dy, dy)), 1e-4f);
        const float d  = __fsqrt_rn(d2);
        return ((unsigned long long)__float_as_uint(d) << 32) | (unsigned)j;
    };

    // bitonic-sort seed (batch 0), ascending across lanes
    unsigned long long R = make_key(lane);
#pragma unroll
    for (int k = 2; k <= 32; k <<= 1) {
#pragma unroll
        for (int jj = k >> 1; jj > 0; jj >>= 1) {
            const unsigned long long other = __shfl_xor_sync(FULL, R, jj);
            const bool takeMin = (((lane & jj) == 0) == ((lane & k) == 0));
            const unsigned long long mn = (R < other) ? R : other;
            const unsigned long long mx = (R < other) ? other : R;
            R = takeMin ? mn : mx;
        }
    }
    unsigned long long keyMax = __shfl_sync(FULL, R, 31);

    // remaining batches: ballot early-reject + serial sorted insert
#pragma unroll 2
    for (int base = 32; base < n; base += 32) {
        const unsigned long long key = make_key(base + lane);
        unsigned cm = __ballot_sync(FULL, key < keyMax);
        if (cm) {
            do {
                const int c = __ffs(cm) - 1;
                cm &= cm - 1;
                const unsigned long long k = __shfl_sync(FULL, key, c);
                const int pos = __popc(__ballot_sync(FULL, R < k));
                const unsigned long long up = __shfl_up_sync(FULL, R, 1);
                R = (lane < pos) ? R : (lane == pos ? k : up);
            } while (cm);
            keyMax = __shfl_sync(FULL, R, 31);
        }
    }

    g_nbr[i * 32 + lane] = (unsigned)(R & 0xffffffffull);
}

// ============================================================================
// Kernel B: features + conv1 + block-GEMM conv2 + argmax + MLP.
// Identical math to the proven R11 kernel (bitwise).
// ============================================================================
#define KWARPS 8
#define TPB (KWARPS * 32)
#define WSCR_FLOATS 272

__global__ __launch_bounds__(TPB, 2) void conv_mlp_kernel(
    const float* __restrict__ states, const float* __restrict__ goals,
    const float* __restrict__ W1, const float* __restrict__ b1,
    const float* __restrict__ W2, const float* __restrict__ b2,
    const float* __restrict__ Wd1, const float* __restrict__ bd1,
    const float* __restrict__ Wd2, const float* __restrict__ bd2,
    const float* __restrict__ Wd3, const float* __restrict__ bd3,
    const float* __restrict__ Wd4, const float* __restrict__ bd4,
    float* __restrict__ out, int n)
{
    extern __shared__ float smem[];
    float* O1s   = smem;                   // 16384
    float* W2Ts  = O1s + 16384;            // 8448 (row stride 132)
    float* W1s   = W2Ts + 8448;            // 320
    float* b1s   = W1s + 320;              // 64
    float* b2s   = b1s + 64;               // 128
    float* msks  = b2s + 128;              // 256
    float* featS = msks + 256;             // 1056 (8 x 132)
    float* wscr0 = featS + 1056;           // 8 x 272

    const int tid  = threadIdx.x;
    const int lane = tid & 31;
    const int warp = tid >> 5;

    const float4* st4 = (const float4*)states;

    for (int idx = tid; idx < 8192; idx += TPB) {
        const int q = idx >> 6, c = idx & 63;
        W2Ts[c * 132 + q] = W2[idx];
    }
    for (int j = tid; j < 320; j += TPB) W1s[j] = W1[j];
    for (int j = tid; j < 64;  j += TPB) b1s[j] = b1[j];
    for (int j = tid; j < 128; j += TPB) b2s[j] = b2[j];
    __syncthreads();

    const int i = blockIdx.x * KWARPS + warp;
    const bool active = (i < n);

    float* wscr = wscr0 + warp * WSCR_FLOATS;
    float* xks  = wscr;          // 160 (dead after conv1)
    float* z1s  = wscr;          // 64  (aliases xks)
    float* z2s  = wscr + 64;     // 128
    float* z3s  = wscr + 192;    // 64
    float* kS   = wscr + 256;    // 4

    float4 si = make_float4(0.f, 0.f, 0.f, 0.f);

    if (active) {
        si = st4[i];

        // neighbor features from precomputed rank-ordered indices
        const int j = (int)g_nbr[i * 32 + lane];
        const float4 sj = st4[j];
        const float x0 = si.x - sj.x;
        const float x1 = si.y - sj.y;
        const float x2 = si.z - sj.z;
        const float x3 = si.w - sj.w;
        const float x4 = (j == i) ? 1.0f : 0.0f;
        const float dist = __fsqrt_rn(__fadd_rn(__fmul_rn(x0, x0), __fmul_rn(x1, x1)));
        msks[32 * warp + lane] = (dist < 1.0f) ? 1.0f : 0.0f;

        xks[lane * 5 + 0] = x0;
        xks[lane * 5 + 1] = x1;
        xks[lane * 5 + 2] = x2;
        xks[lane * 5 + 3] = x3;
        xks[lane * 5 + 4] = x4;
        __syncwarp();

        // raw reshape [32,5] -> [5,32]: lane = position p
        const float h0 = xks[  0 + lane];
        const float h1 = xks[ 32 + lane];
        const float h2 = xks[ 64 + lane];
        const float h3 = xks[ 96 + lane];
        const float h4 = xks[128 + lane];

        // conv1 5 -> 64, straight to shared
        const int col = 32 * warp + lane;
#pragma unroll 8
        for (int c = 0; c < 64; ++c) {
            const float* w = W1s + c * 5;
            float a = __fmul_rn(w[0], h0);
            a = fmaf(w[1], h1, a);
            a = fmaf(w[2], h2, a);
            a = fmaf(w[3], h3, a);
            a = fmaf(w[4], h4, a);
            a = __fadd_rn(a, b1s[c]);
            O1s[c * 256 + col] = fmaxf(a, 0.0f);
        }

        if (lane == 0) {
            const float2 g = ((const float2*)goals)[i];
            float* fA = featS + warp * 132;
            fA[128] = si.x - g.x;
            fA[129] = si.y - g.y;
            fA[130] = si.z;
            fA[131] = si.w;
        }
    }
    __syncthreads();

    // block GEMM (128q x 256col, k=64) + argmax epilogue
    {
        float mk[8];
        {
            const float4 m0 = *(const float4*)(msks + lane * 8);
            const float4 m1 = *(const float4*)(msks + lane * 8 + 4);
            mk[0] = m0.x; mk[1] = m0.y; mk[2] = m0.z; mk[3] = m0.w;
            mk[4] = m1.x; mk[5] = m1.y; mk[6] = m1.z; mk[7] = m1.w;
        }
        const int agent = lane >> 2;
        const int psub  = (lane & 3) * 8;

        for (int pass = 0; pass < 2; ++pass) {
            const int qbase = pass * 64 + warp * 8;
            float acc[8][8];
#pragma unroll
            for (int a = 0; a < 8; ++a)
#pragma unroll
                for (int b = 0; b < 8; ++b) acc[a][b] = 0.0f;

            const float* wp = W2Ts + qbase;
            const float* op = O1s + lane * 8;
#pragma unroll 2
            for (int c = 0; c < 64; ++c) {
                const float4 wv0 = *(const float4*)(wp + c * 132);
                const float4 wv1 = *(const float4*)(wp + c * 132 + 4);
                const float4 ov0 = *(const float4*)(op + c * 256);
                const float4 ov1 = *(const float4*)(op + c * 256 + 4);
                const float wr[8]  = {wv0.x, wv0.y, wv0.z, wv0.w,
                                      wv1.x, wv1.y, wv1.z, wv1.w};
                const float orr[8] = {ov0.x, ov0.y, ov0.z, ov0.w,
                                      ov1.x, ov1.y, ov1.z, ov1.w};
#pragma unroll
                for (int a = 0; a < 8; ++a)
#pragma unroll
                    for (int b = 0; b < 8; ++b)
                        acc[a][b] = fmaf(wr[a], orr[b], acc[a][b]);
            }

#pragma unroll
            for (int a = 0; a < 8; ++a) {
                const int q = qbase + a;
                const float bq = b2s[q];
                unsigned best = 0u;
                int bp = psub;
#pragma unroll
                for (int b = 0; b < 8; ++b) {
                    const float v = __fmul_rn(
                        fmaxf(__fadd_rn(acc[a][b], bq), 0.0f), mk[b]);
                    const unsigned vb = __float_as_uint(v);
                    if (vb > best) { best = vb; bp = psub + b; }
                }
                unsigned long long key =
                    ((unsigned long long)best << 5) | (unsigned)(31 - bp);
                unsigned long long ok = __shfl_xor_sync(FULL, key, 1);
                key = (ok > key) ? ok : key;
                ok = __shfl_xor_sync(FULL, key, 2);
                key = (ok > key) ? ok : key;
                if ((lane & 3) == 0)
                    featS[agent * 132 + q] = (float)(31 - (int)(key & 31ull));
            }
        }
    }
    __syncthreads();

    // MLP 132 -> 64 -> 128 -> 64 -> 4
    if (!active) return;
    {
        const float* fA = featS + warp * 132;

#pragma unroll
        for (int r = 0; r < 2; ++r) {
            const int nn = lane + 32 * r;
            const float4* w  = (const float4*)(Wd1 + nn * 132);
            const float4* f4 = (const float4*)fA;
            float a = 0.0f;
#pragma unroll
            for (int t = 0; t < 33; ++t) {
                const float4 wv = w[t];
                const float4 fv = f4[t];
                a = fmaf(wv.x, fv.x, a); a = fmaf(wv.y, fv.y, a);
                a = fmaf(wv.z, fv.z, a); a = fmaf(wv.w, fv.w, a);
            }
            a = __fadd_rn(a, bd1[nn]);
            z1s[nn] = fmaxf(a, 0.0f);
        }
        __syncwarp();

#pragma unroll
        for (int r = 0; r < 4; ++r) {
            const int nn = lane + 32 * r;
            const float4* w  = (const float4*)(Wd2 + nn * 64);
            const float4* f4 = (const float4*)z1s;
            float a = 0.0f;
#pragma unroll
            for (int t = 0; t < 16; ++t) {
                const float4 wv = w[t];
                const float4 fv = f4[t];
                a = fmaf(wv.x, fv.x, a); a = fmaf(wv.y, fv.y, a);
                a = fmaf(wv.z, fv.z, a); a = fmaf(wv.w, fv.w, a);
            }
            a = __fadd_rn(a, bd2[nn]);
            z2s[nn] = fmaxf(a, 0.0f);
        }
        __syncwarp();

#pragma unroll
        for (int r = 0; r < 2; ++r) {
            const int nn = lane + 32 * r;
            const float4* w  = (const float4*)(Wd3 + nn * 128);
            const float4* f4 = (const float4*)z2s;
            float a = 0.0f;
#pragma unroll
            for (int t = 0; t < 32; ++t) {
                const float4 wv = w[t];
                const float4 fv = f4[t];
                a = fmaf(wv.x, fv.x, a); a = fmaf(wv.y, fv.y, a);
                a = fmaf(wv.z, fv.z, a); a = fmaf(wv.w, fv.w, a);
            }
            a = __fadd_rn(a, bd3[nn]);
            z3s[nn] = fmaxf(a, 0.0f);
        }
        __syncwarp();

        if (lane < 4) {
            const float4* w  = (const float4*)(Wd4 + lane * 64);
            const float4* f4 = (const float4*)z3s;
            float a = 0.0f;
#pragma unroll
            for (int t = 0; t < 16; ++t) {
                const float4 wv = w[t];
                const float4 fv = f4[t];
                a = fmaf(wv.x, fv.x, a); a = fmaf(wv.y, fv.y, a);
                a = fmaf(wv.z, fv.z, a); a = fmaf(wv.w, fv.w, a);
            }
            a = __fadd_rn(a, bd4[lane]);
            kS[lane] = 2.0f / (1.0f + expf(-a)) + 0.2f;
        }
        __syncwarp();

        if (lane == 0) {
            const float k0 = kS[0], k1 = kS[1], k2 = kS[2], k3 = kS[3];
            const float relx = fA[128], rely = fA[129];
            const float vx = si.z, vy = si.w;
            const float ax = -__fadd_rn(__fmul_rn(k0, relx), __fmul_rn(k1, vx));
            const float ay = -__fadd_rn(__fmul_rn(k2, rely), __fmul_rn(k3, vy));
            ((float2*)out)[i] = make_float2(ax, ay);
        }
    }
}

extern "C" void kernel_launch(void* const* d_in, const int* in_sizes, int n_in,
                              void* d_out, int out_size)
{
    const float* states = (const float*)d_in[0];
    const float* goals  = (const float*)d_in[1];
    const float* W1  = (const float*)d_in[2];
    const float* b1  = (const float*)d_in[3];
    const float* W2  = (const float*)d_in[4];
    const float* b2  = (const float*)d_in[5];
    const float* Wd1 = (const float*)d_in[6];
    const float* bd1 = (const float*)d_in[7];
    const float* Wd2 = (const float*)d_in[8];
    const float* bd2 = (const float*)d_in[9];
    const float* Wd3 = (const float*)d_in[10];
    const float* bd3 = (const float*)d_in[11];
    const float* Wd4 = (const float*)d_in[12];
    const float* bd4 = (const float*)d_in[13];

    const int n = in_sizes[0] / 4;

    // Kernel A: top-K
    {
        const int blocks = (n + A_WARPS - 1) / A_WARPS;
        const size_t smemA = (size_t)n * sizeof(float2);
        cudaFuncSetAttribute(topk_kernel,
                             cudaFuncAttributeMaxDynamicSharedMemorySize, (int)smemA);
        topk_kernel<<<blocks, A_TPB, smemA>>>(states, n);
    }

    // Kernel B: features + conv + MLP
    {
        const int blocks = (n + KWARPS - 1) / KWARPS;
        const size_t smem_floats = 16384 + 8448 + 320 + 64 + 128 + 256 + 1056
                                 + (size_t)KWARPS * WSCR_FLOATS;
        const size_t smemB = smem_floats * sizeof(float);
        cudaFuncSetAttribute(conv_mlp_kernel,
                             cudaFuncAttributeMaxDynamicSharedMemorySize, (int)smemB);
        conv_mlp_kernel<<<blocks, TPB, smemB>>>(
            states, goals, W1, b1, W2, b2,
            Wd1, bd1, Wd2, bd2, Wd3, bd3, Wd4, bd4,
            (float*)d_out, n);
    }
}

// round 14
// speedup vs baseline: 1.5948x; 1.0593x over previous
#include <cuda_runtime.h>

#define FULL 0xffffffffu

// ---------------- scratch for neighbor indices (no allocation) --------------
#define MAXN 8192
__device__ unsigned g_nbr[MAXN * 32];

// ============================================================================
// Kernel A: top-32 nearest neighbors per agent (one warp per agent).
// ============================================================================
#define A_WARPS 16
#define A_TPB (A_WARPS * 32)

__global__ __launch_bounds__(A_TPB, 2) void topk_kernel(
    const float* __restrict__ states, int n)
{
    extern __shared__ float2 sxy[];
    const int tid  = threadIdx.x;
    const int lane = tid & 31;
    const int warp = tid >> 5;

    for (int j = tid; j < n; j += A_TPB) {
        const float4 s = ((const float4*)states)[j];
        sxy[j] = make_float2(s.x, s.y);
    }
    __syncthreads();

    const int i = blockIdx.x * A_WARPS + warp;
    if (i >= n) return;

    const float2 pi = sxy[i];
    const float six = pi.x, siy = pi.y;

    auto make_key = [&](int j) -> unsigned long long {
        const float2 p = sxy[j];
        const float dx = six - p.x;
        const float dy = siy - p.y;
        const float d2 = __fadd_rn(__fadd_rn(__fmul_rn(dx, dx), __fmul_rn(dy, dy)), 1e-4f);
        const float d  = __fsqrt_rn(d2);
        return ((unsigned long long)__float_as_uint(d) << 32) | (unsigned)j;
    };

    unsigned long long R = make_key(lane);
#pragma unroll
    for (int k = 2; k <= 32; k <<= 1) {
#pragma unroll
        for (int jj = k >> 1; jj > 0; jj >>= 1) {
            const unsigned long long other = __shfl_xor_sync(FULL, R, jj);
            const bool takeMin = (((lane & jj) == 0) == ((lane & k) == 0));
            const unsigned long long mn = (R < other) ? R : other;
            const unsigned long long mx = (R < other) ? other : R;
            R = takeMin ? mn : mx;
        }
    }
    unsigned long long keyMax = __shfl_sync(FULL, R, 31);

#pragma unroll 2
    for (int base = 32; base < n; base += 32) {
        const unsigned long long key = make_key(base + lane);
        unsigned cm = __ballot_sync(FULL, key < keyMax);
        if (cm) {
            do {
                const int c = __ffs(cm) - 1;
                cm &= cm - 1;
                const unsigned long long k = __shfl_sync(FULL, key, c);
                const int pos = __popc(__ballot_sync(FULL, R < k));
                const unsigned long long up = __shfl_up_sync(FULL, R, 1);
                R = (lane < pos) ? R : (lane == pos ? k : up);
            } while (cm);
            keyMax = __shfl_sync(FULL, R, 31);
        }
    }

    g_nbr[i * 32 + lane] = (unsigned)(R & 0xffffffffull);
}

// ============================================================================
// Kernel B: features + conv1 + block-GEMM conv2 + argmax + cooperative MLP.
// conv path bitwise-identical to proven R11/R12; MLP reassociated (safe).
// ============================================================================
#define KWARPS 8
#define TPB (KWARPS * 32)
#define WSCR_FLOATS 272
// union region: phase3 O1s(16384)+W2Ts(8448)+W1s(320)+b1s(64)+b2s(128)=25344
//               phase4 Wd1s(8448)+Wd2s(8192)+Wd3s(8192)+Wd4s(256)=25088
#define UNION_FLOATS 25344

__global__ __launch_bounds__(TPB, 2) void conv_mlp_kernel(
    const float* __restrict__ states, const float* __restrict__ goals,
    const float* __restrict__ W1, const float* __restrict__ b1,
    const float* __restrict__ W2, const float* __restrict__ b2,
    const float* __restrict__ Wd1, const float* __restrict__ bd1,
    const float* __restrict__ Wd2, const float* __restrict__ bd2,
    const float* __restrict__ Wd3, const float* __restrict__ bd3,
    const float* __restrict__ Wd4, const float* __restrict__ bd4,
    float* __restrict__ out, int n)
{
    extern __shared__ float smem[];
    float* U     = smem;                   // union region
    float* O1s   = U;                      // 16384 (phase 3)
    float* W2Ts  = U + 16384;              // 8448  (phase 3, stride 132)
    float* W1s   = U + 24832;              // 320   (phase 3)
    float* b1s   = U + 25152;              // 64    (phase 3)
    float* b2s   = U + 25216;              // 128   (phase 3)
    float* Wd1s  = U;                      // 8448  (phase 4)
    float* Wd2s  = U + 8448;               // 8192  (phase 4)
    float* Wd3s  = U + 16640;              // 8192  (phase 4)
    float* Wd4s  = U + 24832;              // 256   (phase 4)
    float* msks  = U + UNION_FLOATS;       // 256
    float* featS = msks + 256;             // 1056 (8 x 132)
    float* wscr0 = featS + 1056;           // 8 x 272

    const int tid  = threadIdx.x;
    const int lane = tid & 31;
    const int warp = tid >> 5;

    const float4* st4 = (const float4*)states;

    for (int idx = tid; idx < 8192; idx += TPB) {
        const int q = idx >> 6, c = idx & 63;
        W2Ts[c * 132 + q] = W2[idx];
    }
    for (int j = tid; j < 320; j += TPB) W1s[j] = W1[j];
    for (int j = tid; j < 64;  j += TPB) b1s[j] = b1[j];
    for (int j = tid; j < 128; j += TPB) b2s[j] = b2[j];
    __syncthreads();

    const int i = blockIdx.x * KWARPS + warp;
    const bool active = (i < n);

    float* wscr = wscr0 + warp * WSCR_FLOATS;
    float* xks  = wscr;          // 160 (dead after conv1)
    float* z1s  = wscr;          // 64  (aliases xks)
    float* z2s  = wscr + 64;     // 128
    float* z3s  = wscr + 192;    // 64
    float* kS   = wscr + 256;    // 4

    float4 si = make_float4(0.f, 0.f, 0.f, 0.f);

    if (active) {
        si = st4[i];

        const int j = (int)g_nbr[i * 32 + lane];
        const float4 sj = st4[j];
        const float x0 = si.x - sj.x;
        const float x1 = si.y - sj.y;
        const float x2 = si.z - sj.z;
        const float x3 = si.w - sj.w;
        const float x4 = (j == i) ? 1.0f : 0.0f;
        const float dist = __fsqrt_rn(__fadd_rn(__fmul_rn(x0, x0), __fmul_rn(x1, x1)));
        msks[32 * warp + lane] = (dist < 1.0f) ? 1.0f : 0.0f;

        xks[lane * 5 + 0] = x0;
        xks[lane * 5 + 1] = x1;
        xks[lane * 5 + 2] = x2;
        xks[lane * 5 + 3] = x3;
        xks[lane * 5 + 4] = x4;
        __syncwarp();

        // raw reshape [32,5] -> [5,32]: lane = position p
        const float h0 = xks[  0 + lane];
        const float h1 = xks[ 32 + lane];
        const float h2 = xks[ 64 + lane];
        const float h3 = xks[ 96 + lane];
        const float h4 = xks[128 + lane];

        // conv1 5 -> 64 (bitwise-exact chain), to shared
        const int col = 32 * warp + lane;
#pragma unroll 8
        for (int c = 0; c < 64; ++c) {
            const float* w = W1s + c * 5;
            float a = __fmul_rn(w[0], h0);
            a = fmaf(w[1], h1, a);
            a = fmaf(w[2], h2, a);
            a = fmaf(w[3], h3, a);
            a = fmaf(w[4], h4, a);
            a = __fadd_rn(a, b1s[c]);
            O1s[c * 256 + col] = fmaxf(a, 0.0f);
        }

        if (lane == 0) {
            const float2 g = ((const float2*)goals)[i];
            float* fA = featS + warp * 132;
            fA[128] = si.x - g.x;
            fA[129] = si.y - g.y;
            fA[130] = si.z;
            fA[131] = si.w;
        }
    }
    __syncthreads();

    // -------- block GEMM (128q x 256col, k=64), conflict-free O1 loads ------
    // thread cols: {lane*4 .. +3} (agent A = lane>>3) and {128+lane*4 .. +3}
    // (agent A+4). Per-output fmaf order c=0..63 + bias: bitwise exact.
    {
        float mk[8];
        {
            const float4 m0 = *(const float4*)(msks + lane * 4);
            const float4 m1 = *(const float4*)(msks + 128 + lane * 4);
            mk[0] = m0.x; mk[1] = m0.y; mk[2] = m0.z; mk[3] = m0.w;
            mk[4] = m1.x; mk[5] = m1.y; mk[6] = m1.z; mk[7] = m1.w;
        }
        const int agentA = lane >> 3;            // 0..3
        const int psub   = (lane & 7) * 4;       // first position of this thread

        for (int pass = 0; pass < 2; ++pass) {
            const int qbase = pass * 64 + warp * 8;
            float acc[8][8];
#pragma unroll
            for (int a = 0; a < 8; ++a)
#pragma unroll
                for (int b = 0; b < 8; ++b) acc[a][b] = 0.0f;

            const float* wp = W2Ts + qbase;
#pragma unroll 2
            for (int c = 0; c < 64; ++c) {
                const float4 wv0 = *(const float4*)(wp + c * 132);
                const float4 wv1 = *(const float4*)(wp + c * 132 + 4);
                const float4 ov0 = *(const float4*)(O1s + c * 256 + lane * 4);
                const float4 ov1 = *(const float4*)(O1s + c * 256 + 128 + lane * 4);
                const float wr[8]  = {wv0.x, wv0.y, wv0.z, wv0.w,
                                      wv1.x, wv1.y, wv1.z, wv1.w};
                const float orr[8] = {ov0.x, ov0.y, ov0.z, ov0.w,
                                      ov1.x, ov1.y, ov1.z, ov1.w};
#pragma unroll
                for (int a = 0; a < 8; ++a)
#pragma unroll
                    for (int b = 0; b < 8; ++b)
                        acc[a][b] = fmaf(wr[a], orr[b], acc[a][b]);
            }

#pragma unroll
            for (int a = 0; a < 8; ++a) {
                const int q = qbase + a;
                const float bq = b2s[q];
                // agent A over b=0..3, agent A+4 over b=4..7
                unsigned bestL = 0u; int bpL = psub;
                unsigned bestH = 0u; int bpH = psub;
#pragma unroll
                for (int b = 0; b < 4; ++b) {
                    const float v = __fmul_rn(
                        fmaxf(__fadd_rn(acc[a][b], bq), 0.0f), mk[b]);
                    const unsigned vb = __float_as_uint(v);
                    if (vb > bestL) { bestL = vb; bpL = psub + b; }
                }
#pragma unroll
                for (int b = 4; b < 8; ++b) {
                    const float v = __fmul_rn(
                        fmaxf(__fadd_rn(acc[a][b], bq), 0.0f), mk[b]);
                    const unsigned vb = __float_as_uint(v);
                    if (vb > bestH) { bestH = vb; bpH = psub + b - 4; }
                }
                unsigned long long keyL =
                    ((unsigned long long)bestL << 5) | (unsigned)(31 - bpL);
                unsigned long long keyH =
                    ((unsigned long long)bestH << 5) | (unsigned)(31 - bpH);
#pragma unroll
                for (int o = 1; o < 8; o <<= 1) {
                    const unsigned long long oL = __shfl_xor_sync(FULL, keyL, o);
                    const unsigned long long oH = __shfl_xor_sync(FULL, keyH, o);
                    keyL = (oL > keyL) ? oL : keyL;
                    keyH = (oH > keyH) ? oH : keyH;
                }
                if ((lane & 7) == 0) {
                    featS[agentA * 132 + q]       = (float)(31 - (int)(keyL & 31ull));
                    featS[(agentA + 4) * 132 + q] = (float)(31 - (int)(keyH & 31ull));
                }
            }
        }
    }
    __syncthreads();

    // -------- stage MLP weights into the dead union region (once/block) -----
    {
        const float4* s1 = (const float4*)Wd1;   // 2112 float4
        const float4* s2 = (const float4*)Wd2;   // 2048
        const float4* s3 = (const float4*)Wd3;   // 2048
        const float4* s4 = (const float4*)Wd4;   // 64
        float4* d1 = (float4*)Wd1s;
        float4* d2 = (float4*)Wd2s;
        float4* d3 = (float4*)Wd3s;
        float4* d4 = (float4*)Wd4s;
        for (int t = tid; t < 2112; t += TPB) d1[t] = s1[t];
        for (int t = tid; t < 2048; t += TPB) d2[t] = s2[t];
        for (int t = tid; t < 2048; t += TPB) d3[t] = s3[t];
        for (int t = tid; t < 64;   t += TPB) d4[t] = s4[t];
    }
    __syncthreads();

    // -------- cooperative MLP 132 -> 64 -> 128 -> 64 -> 4 (reassociated) ----
    if (!active) return;
    {
        const float* fA = featS + warp * 132;
        const float4 f4 = *(const float4*)(fA + lane * 4);      // inputs 0..127
        const float  ft = (lane < 4) ? fA[128 + lane] : 0.0f;   // tail 128..131

        // layer 1: 132 -> 64, lanes split input, shfl-reduce
        for (int nn = 0; nn < 64; nn += 2) {
#pragma unroll
            for (int s = 0; s < 2; ++s) {
                const int m = nn + s;
                const float4 w = *(const float4*)(Wd1s + m * 132 + lane * 4);
                float p = w.x * f4.x;
                p = fmaf(w.y, f4.y, p);
                p = fmaf(w.z, f4.z, p);
                p = fmaf(w.w, f4.w, p);
                if (lane < 4) p = fmaf(Wd1s[m * 132 + 128 + lane], ft, p);
#pragma unroll
                for (int o = 16; o; o >>= 1) p += __shfl_xor_sync(FULL, p, o);
                if (lane == 0) z1s[m] = fmaxf(p + bd1[m], 0.0f);
            }
        }
        __syncwarp();

        // layer 2: 64 -> 128
        const float2 zv1 = *(const float2*)(z1s + lane * 2);
        for (int nn = 0; nn < 128; nn += 2) {
#pragma unroll
            for (int s = 0; s < 2; ++s) {
                const int m = nn + s;
                const float2 w = *(const float2*)(Wd2s + m * 64 + lane * 2);
                float p = fmaf(w.y, zv1.y, w.x * zv1.x);
#pragma unroll
                for (int o = 16; o; o >>= 1) p += __shfl_xor_sync(FULL, p, o);
                if (lane == 0) z2s[m] = fmaxf(p + bd2[m], 0.0f);
            }
        }
        __syncwarp();

        // layer 3: 128 -> 64
        const float4 zv2 = *(const float4*)(z2s + lane * 4);
        for (int nn = 0; nn < 64; nn += 2) {
#pragma unroll
            for (int s = 0; s < 2; ++s) {
                const int m = nn + s;
                const float4 w = *(const float4*)(Wd3s + m * 128 + lane * 4);
                float p = w.x * zv2.x;
                p = fmaf(w.y, zv2.y, p);
                p = fmaf(w.z, zv2.z, p);
                p = fmaf(w.w, zv2.w, p);
#pragma unroll
                for (int o = 16; o; o >>= 1) p += __shfl_xor_sync(FULL, p, o);
                if (lane == 0) z3s[m] = fmaxf(p + bd3[m], 0.0f);
            }
        }
        __syncwarp();

        // layer 4: 64 -> 4 gains
        const float2 zv3 = *(const float2*)(z3s + lane * 2);
#pragma unroll
        for (int m = 0; m < 4; ++m) {
            const float2 w = *(const float2*)(Wd4s + m * 64 + lane * 2);
            float p = fmaf(w.y, zv3.y, w.x * zv3.x);
#pragma unroll
            for (int o = 16; o; o >>= 1) p += __shfl_xor_sync(FULL, p, o);
            if (lane == 0)
                kS[m] = 2.0f / (1.0f + expf(-(p + bd4[m]))) + 0.2f;
        }
        __syncwarp();

        if (lane == 0) {
            const float k0 = kS[0], k1 = kS[1], k2 = kS[2], k3 = kS[3];
            const float relx = fA[128], rely = fA[129];
            const float vx = si.z, vy = si.w;
            const float ax = -__fadd_rn(__fmul_rn(k0, relx), __fmul_rn(k1, vx));
            const float ay = -__fadd_rn(__fmul_rn(k2, rely), __fmul_rn(k3, vy));
            ((float2*)out)[i] = make_float2(ax, ay);
        }
    }
}

extern "C" void kernel_launch(void* const* d_in, const int* in_sizes, int n_in,
                              void* d_out, int out_size)
{
    const float* states = (const float*)d_in[0];
    const float* goals  = (const float*)d_in[1];
    const float* W1  = (const float*)d_in[2];
    const float* b1  = (const float*)d_in[3];
    const float* W2  = (const float*)d_in[4];
    const float* b2  = (const float*)d_in[5];
    const float* Wd1 = (const float*)d_in[6];
    const float* bd1 = (const float*)d_in[7];
    const float* Wd2 = (const float*)d_in[8];
    const float* bd2 = (const float*)d_in[9];
    const float* Wd3 = (const float*)d_in[10];
    const float* bd3 = (const float*)d_in[11];
    const float* Wd4 = (const float*)d_in[12];
    const float* bd4 = (const float*)d_in[13];

    const int n = in_sizes[0] / 4;

    // Kernel A: top-K
    {
        const int blocks = (n + A_WARPS - 1) / A_WARPS;
        const size_t smemA = (size_t)n * sizeof(float2);
        cudaFuncSetAttribute(topk_kernel,
                             cudaFuncAttributeMaxDynamicSharedMemorySize, (int)smemA);
        topk_kernel<<<blocks, A_TPB, smemA>>>(states, n);
    }

    // Kernel B: features + conv + MLP
    {
        const int blocks = (n + KWARPS - 1) / KWARPS;
        const size_t smem_floats = UNION_FLOATS + 256 + 1056
                                 + (size_t)KWARPS * WSCR_FLOATS;
        const size_t smemB = smem_floats * sizeof(float);
        cudaFuncSetAttribute(conv_mlp_kernel,
                             cudaFuncAttributeMaxDynamicSharedMemorySize, (int)smemB);
        conv_mlp_kernel<<<blocks, TPB, smemB>>>(
            states, goals, W1, b1, W2, b2,
            Wd1, bd1, Wd2, bd2, Wd3, bd3, Wd4, bd4,
            (float*)d_out, n);
    }
}